// round 9
// baseline (speedup 1.0000x reference)
#include <cuda_runtime.h>

#define N 384
#define N2 (2 * N)
#define D 256
#define EPSF 1e-12f
#define NTILES 21
#define NUNITS (NTILES * N)   // 8064
#define NBLK 296
#define BI 8                  // i-batch staged in smem

typedef unsigned long long u64;

// scratch (no allocation allowed)
__device__ float  g_Gs[N * N];
__device__ float  g_Gt[N * N];
__device__ float  g_ps[N * N];      // p = inv_ij      (plain, k-side q)
__device__ float  g_nrqs[N * N];    // -G_ij * p       (plain, k-side)
__device__ float  g_psd[N * N2];    // {p,p}           (dup, j-side)
__device__ float  g_cpsd[N * N2];   // {cp,cp}         (dup, j-side)
__device__ float  g_pt[N * N];
__device__ float  g_nrqt[N * N];
__device__ float  g_ptd[N * N2];
__device__ float  g_cptd[N * N2];
__device__ double g_sum;
__device__ int    g_cnt;

// upper-triangle 64x64 tile enumeration (a <= b), 21 tiles over a 6x6 grid
__constant__ int c_TA[NTILES] = {0,0,0,0,0,0,1,1,1,1,1,2,2,2,2,3,3,3,4,4,5};
__constant__ int c_TB[NTILES] = {0,1,2,3,4,5,1,2,3,4,5,2,3,4,5,3,4,5,4,5,5};

// ---------------------------------------------------------------------------
// packed f32x2 helpers (sm_103a)
__device__ __forceinline__ float2 unpack2(u64 v) {
    float2 f; asm("mov.b64 {%0,%1},%2;" : "=f"(f.x), "=f"(f.y) : "l"(v)); return f;
}
__device__ __forceinline__ u64 mul2(u64 a, u64 b) {
    u64 r; asm("mul.rn.f32x2 %0,%1,%2;" : "=l"(r) : "l"(a), "l"(b)); return r;
}
__device__ __forceinline__ u64 fma2(u64 a, u64 b, u64 c) {
    u64 r; asm("fma.rn.f32x2 %0,%1,%2,%3;" : "=l"(r) : "l"(a), "l"(b), "l"(c)); return r;
}

// ---------------------------------------------------------------------------
// Fused Gram + prep with double-buffered smem (1 sync per 32-k chunk).
// Epilogue emits G, plain p/nr, and j-side duplicated pd/cpd arrays.
// grid (6, 12, 2), 256 threads, 2x4 microtile.
__global__ void __launch_bounds__(256) rkd_gram_prep_kernel(const float* __restrict__ S,
                                                            const float* __restrict__ T) {
    const float* __restrict__ E = (blockIdx.z == 0) ? S : T;
    float* __restrict__ G   = (blockIdx.z == 0) ? g_Gs   : g_Gt;
    float* __restrict__ P   = (blockIdx.z == 0) ? g_ps   : g_pt;
    float* __restrict__ NR  = (blockIdx.z == 0) ? g_nrqs : g_nrqt;
    float* __restrict__ PD  = (blockIdx.z == 0) ? g_psd  : g_ptd;
    float* __restrict__ CPD = (blockIdx.z == 0) ? g_cpsd : g_cptd;

    __shared__ float As[2][32][34];
    __shared__ float Bs[2][32][68];
    __shared__ float dA[32];
    __shared__ float dB[64];

    int tid = threadIdx.x;
    if (blockIdx.x == 0 && blockIdx.y == 0 && blockIdx.z == 0 && tid == 0) {
        g_sum = 0.0; g_cnt = 0;
    }

    int ty = tid >> 4, tx = tid & 15;
    int row = tid >> 3;
    int c4 = (tid & 7) * 4;

    int tj = blockIdx.y * 32, tk = blockIdx.x * 64;

    const float* pA  = &E[(tj + row) * D + c4];
    const float* pB0 = &E[(tk + row) * D + c4];
    const float* pB1 = &E[(tk + 32 + row) * D + c4];

    float acc[2][4];
#pragma unroll
    for (int r = 0; r < 2; r++)
#pragma unroll
        for (int c = 0; c < 4; c++) acc[r][c] = 0.f;

    float ssA = 0.f, ssB0 = 0.f, ssB1 = 0.f;

    float4 av  = *reinterpret_cast<const float4*>(pA);
    float4 bv0 = *reinterpret_cast<const float4*>(pB0);
    float4 bv1 = *reinterpret_cast<const float4*>(pB1);
    As[0][c4 + 0][row] = av.x;  As[0][c4 + 1][row] = av.y;
    As[0][c4 + 2][row] = av.z;  As[0][c4 + 3][row] = av.w;
    Bs[0][c4 + 0][row] = bv0.x; Bs[0][c4 + 1][row] = bv0.y;
    Bs[0][c4 + 2][row] = bv0.z; Bs[0][c4 + 3][row] = bv0.w;
    Bs[0][c4 + 0][row + 32] = bv1.x; Bs[0][c4 + 1][row + 32] = bv1.y;
    Bs[0][c4 + 2][row + 32] = bv1.z; Bs[0][c4 + 3][row + 32] = bv1.w;
    ssA  = fmaf(av.x,  av.x,  fmaf(av.y,  av.y,  fmaf(av.z,  av.z,  fmaf(av.w,  av.w,  ssA))));
    ssB0 = fmaf(bv0.x, bv0.x, fmaf(bv0.y, bv0.y, fmaf(bv0.z, bv0.z, fmaf(bv0.w, bv0.w, ssB0))));
    ssB1 = fmaf(bv1.x, bv1.x, fmaf(bv1.y, bv1.y, fmaf(bv1.z, bv1.z, fmaf(bv1.w, bv1.w, ssB1))));
    __syncthreads();

#pragma unroll
    for (int chunk = 0; chunk < D / 32; chunk++) {
        int cur = chunk & 1;
        bool more = (chunk < D / 32 - 1);
        if (more) {
            int off = (chunk + 1) * 32;
            av  = *reinterpret_cast<const float4*>(pA  + off);
            bv0 = *reinterpret_cast<const float4*>(pB0 + off);
            bv1 = *reinterpret_cast<const float4*>(pB1 + off);
        }
#pragma unroll
        for (int kk = 0; kk < 32; kk++) {
            float2 a2 = *reinterpret_cast<const float2*>(&As[cur][kk][ty * 2]);
            float4 b4 = *reinterpret_cast<const float4*>(&Bs[cur][kk][tx * 4]);
            acc[0][0] = fmaf(a2.x, b4.x, acc[0][0]);
            acc[0][1] = fmaf(a2.x, b4.y, acc[0][1]);
            acc[0][2] = fmaf(a2.x, b4.z, acc[0][2]);
            acc[0][3] = fmaf(a2.x, b4.w, acc[0][3]);
            acc[1][0] = fmaf(a2.y, b4.x, acc[1][0]);
            acc[1][1] = fmaf(a2.y, b4.y, acc[1][1]);
            acc[1][2] = fmaf(a2.y, b4.z, acc[1][2]);
            acc[1][3] = fmaf(a2.y, b4.w, acc[1][3]);
        }
        if (more) {
            int nb = cur ^ 1;
            As[nb][c4 + 0][row] = av.x;  As[nb][c4 + 1][row] = av.y;
            As[nb][c4 + 2][row] = av.z;  As[nb][c4 + 3][row] = av.w;
            Bs[nb][c4 + 0][row] = bv0.x; Bs[nb][c4 + 1][row] = bv0.y;
            Bs[nb][c4 + 2][row] = bv0.z; Bs[nb][c4 + 3][row] = bv0.w;
            Bs[nb][c4 + 0][row + 32] = bv1.x; Bs[nb][c4 + 1][row + 32] = bv1.y;
            Bs[nb][c4 + 2][row + 32] = bv1.z; Bs[nb][c4 + 3][row + 32] = bv1.w;
            ssA  = fmaf(av.x,  av.x,  fmaf(av.y,  av.y,  fmaf(av.z,  av.z,  fmaf(av.w,  av.w,  ssA))));
            ssB0 = fmaf(bv0.x, bv0.x, fmaf(bv0.y, bv0.y, fmaf(bv0.z, bv0.z, fmaf(bv0.w, bv0.w, ssB0))));
            ssB1 = fmaf(bv1.x, bv1.x, fmaf(bv1.y, bv1.y, fmaf(bv1.z, bv1.z, fmaf(bv1.w, bv1.w, ssB1))));
        }
        __syncthreads();
    }

#pragma unroll
    for (int m = 4; m > 0; m >>= 1) {
        ssA  += __shfl_xor_sync(0xffffffffu, ssA,  m, 8);
        ssB0 += __shfl_xor_sync(0xffffffffu, ssB0, m, 8);
        ssB1 += __shfl_xor_sync(0xffffffffu, ssB1, m, 8);
    }
    if ((tid & 7) == 0) {
        dA[row] = ssA;
        dB[row] = ssB0;
        dB[row + 32] = ssB1;
    }
    __syncthreads();

    int jg = tj + ty * 2;
    int kg = tk + tx * 4;
#pragma unroll
    for (int r = 0; r < 2; r++) {
        int ig = jg + r;
        float di = dA[ty * 2 + r];

        float p[4], cp[4], nr[4];
#pragma unroll
        for (int c = 0; c < 4; c++) {
            float gij = acc[r][c];
            float dj = dB[tx * 4 + c];
            float cs = di - gij;
            float n2 = fmaxf((dj - gij) + cs, 0.f);
            float pv = (ig == kg + c) ? 0.f : (1.f / fmaxf(sqrtf(n2), EPSF));
            p[c] = pv;
            cp[c] = cs * pv;
            nr[c] = -gij * pv;
        }
        *reinterpret_cast<float4*>(&G[ig * N + kg]) =
            make_float4(acc[r][0], acc[r][1], acc[r][2], acc[r][3]);
        *reinterpret_cast<float4*>(&P[ig * N + kg])  = make_float4(p[0], p[1], p[2], p[3]);
        *reinterpret_cast<float4*>(&NR[ig * N + kg]) = make_float4(nr[0], nr[1], nr[2], nr[3]);
        *reinterpret_cast<float4*>(&PD[ig * N2 + 2 * kg])      = make_float4(p[0], p[0], p[1], p[1]);
        *reinterpret_cast<float4*>(&PD[ig * N2 + 2 * kg + 4])  = make_float4(p[2], p[2], p[3], p[3]);
        *reinterpret_cast<float4*>(&CPD[ig * N2 + 2 * kg])     = make_float4(cp[0], cp[0], cp[1], cp[1]);
        *reinterpret_cast<float4*>(&CPD[ig * N2 + 2 * kg + 4]) = make_float4(cp[2], cp[2], cp[3], cp[3]);
    }
}

// ---------------------------------------------------------------------------
// Main: smem-staged slices; j-side arrives pre-duplicated so the math body
// contains ZERO register-pair pack movs: 12 LDS.128 + packed math per anchor.
__global__ void __launch_bounds__(256, 2) rkd_angle_loss_kernel(float* __restrict__ out) {
    // J slices duplicated (128 floats/i): 0:pd_s 1:cpd_s 2:pd_t 3:cpd_t
    __shared__ float stJ[4][BI][128];
    // K slices plain (64 floats/i):       0:p_s  1:nr_s  2:p_t  3:nr_t
    __shared__ float stK[4][BI][64];
    __shared__ float red[256];

    int tid = threadIdx.x;
    int ty = tid >> 4, tx = tid & 15;
    int b = blockIdx.x;

    // staging decomposition (constant per thread)
    int jl_ii = (tid >> 5) & 7;       // J loads: i within batch
    int jl_c4 = (tid & 31) * 4;       // J loads: col (0..124)
    int kl_ii = (tid >> 4) & 7;       // K loads: i within batch
    int kl_c4 = (tid & 15) * 4;       // K loads: col (0..60)
    int kl_s0 = (tid >> 7) & 1;       // K load t=0 -> slice 0/1
                                      // K load t=1 -> slice 2/3 (same bit)

    int u0 = (b * NUNITS) / NBLK;
    int u1 = ((b + 1) * NUNITS) / NBLK;
    int tile = u0 / N;
    int i = u0 - tile * N;
    int remaining = u1 - u0;

    const u64 NEG1 = 0xBF800000BF800000ULL;  // {-1.f, -1.f}

    float wacc = 0.f;

    while (remaining > 0) {
        int cnt = min(N - i, remaining);
        remaining -= cnt;

        int tj = c_TA[tile] * 64;
        int tk = c_TB[tile] * 64;
        int jq = tj + ty * 4;
        int kq = tk + tx * 4;

        // staging source pointers for this tile (row offset added per batch)
        const float* jsrc0 = g_psd  + tj * 2 + jl_c4;
        const float* jsrc1 = g_cpsd + tj * 2 + jl_c4;
        const float* jsrc2 = g_ptd  + tj * 2 + jl_c4;
        const float* jsrc3 = g_cptd + tj * 2 + jl_c4;
        const float* ksrc0 = (kl_s0 ? g_nrqs : g_ps) + tk + kl_c4;
        const float* ksrc1 = (kl_s0 ? g_nrqt : g_pt) + tk + kl_c4;

        // G microtile packed along k (free ulonglong2 reinterpret)
        u64 G2s[4][2], G2t[4][2];
#pragma unroll
        for (int jj = 0; jj < 4; jj++) {
            ulonglong2 vs = *reinterpret_cast<const ulonglong2*>(&g_Gs[(jq + jj) * N + kq]);
            ulonglong2 vt = *reinterpret_cast<const ulonglong2*>(&g_Gt[(jq + jj) * N + kq]);
            G2s[jj][0] = vs.x; G2s[jj][1] = vs.y;
            G2t[jj][0] = vt.x; G2t[jj][1] = vt.y;
        }

        float acc0 = 0.f, acc1 = 0.f;

        for (int s = 0; s < cnt; s += BI) {
            // ---- cooperative stage of BI rows (clamped; clamp rows unused) ----
            {
                int jr = min(i + s + jl_ii, N - 1) * N2;
                int kr = min(i + s + kl_ii, N - 1) * N;
                float4 j0 = *reinterpret_cast<const float4*>(jsrc0 + jr);
                float4 j1 = *reinterpret_cast<const float4*>(jsrc1 + jr);
                float4 j2 = *reinterpret_cast<const float4*>(jsrc2 + jr);
                float4 j3 = *reinterpret_cast<const float4*>(jsrc3 + jr);
                float4 k0 = *reinterpret_cast<const float4*>(ksrc0 + kr);
                float4 k1 = *reinterpret_cast<const float4*>(ksrc1 + kr);
                *reinterpret_cast<float4*>(&stJ[0][jl_ii][jl_c4]) = j0;
                *reinterpret_cast<float4*>(&stJ[1][jl_ii][jl_c4]) = j1;
                *reinterpret_cast<float4*>(&stJ[2][jl_ii][jl_c4]) = j2;
                *reinterpret_cast<float4*>(&stJ[3][jl_ii][jl_c4]) = j3;
                *reinterpret_cast<float4*>(&stK[0 + kl_s0][kl_ii][kl_c4]) = k0;
                *reinterpret_cast<float4*>(&stK[2 + kl_s0][kl_ii][kl_c4]) = k1;
            }
            __syncthreads();

            int bi = min(BI, cnt - s);
            for (int ii = 0; ii < bi; ii++) {
                // j-side broadcast pairs, pre-duplicated (2 LDS.128 each)
                ulonglong2 pa = *reinterpret_cast<const ulonglong2*>(&stJ[0][ii][ty * 8]);
                ulonglong2 pb = *reinterpret_cast<const ulonglong2*>(&stJ[0][ii][ty * 8 + 4]);
                ulonglong2 ca = *reinterpret_cast<const ulonglong2*>(&stJ[1][ii][ty * 8]);
                ulonglong2 cb = *reinterpret_cast<const ulonglong2*>(&stJ[1][ii][ty * 8 + 4]);
                ulonglong2 pc = *reinterpret_cast<const ulonglong2*>(&stJ[2][ii][ty * 8]);
                ulonglong2 pd = *reinterpret_cast<const ulonglong2*>(&stJ[2][ii][ty * 8 + 4]);
                ulonglong2 cc = *reinterpret_cast<const ulonglong2*>(&stJ[3][ii][ty * 8]);
                ulonglong2 cd = *reinterpret_cast<const ulonglong2*>(&stJ[3][ii][ty * 8 + 4]);
                // k-side natural pairs (1 LDS.128 each)
                ulonglong2 qs = *reinterpret_cast<const ulonglong2*>(&stK[0][ii][tx * 4]);
                ulonglong2 ns = *reinterpret_cast<const ulonglong2*>(&stK[1][ii][tx * 4]);
                ulonglong2 qt = *reinterpret_cast<const ulonglong2*>(&stK[2][ii][tx * 4]);
                ulonglong2 nt = *reinterpret_cast<const ulonglong2*>(&stK[3][ii][tx * 4]);

                u64 p2s[4] = { pa.x, pa.y, pb.x, pb.y };
                u64 c2s[4] = { ca.x, ca.y, cb.x, cb.y };
                u64 p2t[4] = { pc.x, pc.y, pd.x, pd.y };
                u64 c2t[4] = { cc.x, cc.y, cd.x, cd.y };
                u64 q2s[2] = { qs.x, qs.y };
                u64 n2s[2] = { ns.x, ns.y };
                u64 q2t[2] = { qt.x, qt.y };
                u64 n2t[2] = { nt.x, nt.y };

#pragma unroll
                for (int jj = 0; jj < 4; jj++) {
#pragma unroll
                    for (int p = 0; p < 2; p++) {
                        u64 t2s = fma2(p2s[jj], G2s[jj][p], c2s[jj]);
                        u64 m2s = mul2(n2s[p], p2s[jj]);
                        u64 a2s = fma2(q2s[p], t2s, m2s);
                        u64 t2t = fma2(p2t[jj], G2t[jj][p], c2t[jj]);
                        u64 m2t = mul2(n2t[p], p2t[jj]);
                        u64 a2t = fma2(q2t[p], t2t, m2t);
                        u64 d2  = fma2(a2t, NEG1, a2s);      // as - at
                        float2 d = unpack2(d2);
                        float x0 = fabsf(d.x), x1 = fabsf(d.y);
                        float y0 = fminf(x0, 1.f), y1 = fminf(x1, 1.f);
                        float t0 = fmaf(y0, -0.5f, x0);
                        float t1 = fmaf(y1, -0.5f, x1);
                        acc0 = fmaf(y0, t0, acc0);
                        acc1 = fmaf(y1, t1, acc1);
                    }
                }
            }
            __syncthreads();
        }

        float w = (c_TA[tile] == c_TB[tile]) ? 1.f : 2.f;
        wacc = fmaf(w, acc0 + acc1, wacc);
        tile++;
        i = 0;
    }

    // block reduction
    red[tid] = wacc;
    __syncthreads();
#pragma unroll
    for (int s = 128; s > 0; s >>= 1) {
        if (tid < s) red[tid] += red[tid + s];
        __syncthreads();
    }
    if (tid == 0) {
        atomicAdd(&g_sum, (double)red[0]);
        __threadfence();
        int t = atomicAdd(&g_cnt, 1);
        if (t == NBLK - 1) {
            double v = atomicAdd(&g_sum, 0.0);
            double n3 = (double)N * (double)N * (double)N;
            out[0] = (float)(v / n3);
        }
    }
}

// ---------------------------------------------------------------------------
extern "C" void kernel_launch(void* const* d_in, const int* in_sizes, int n_in,
                              void* d_out, int out_size) {
    const float* student = (const float*)d_in[0];
    const float* teacher = (const float*)d_in[1];
    float* out = (float*)d_out;

    dim3 ggrd(N / 64, N / 32, 2);
    rkd_gram_prep_kernel<<<ggrd, 256>>>(student, teacher);

    rkd_angle_loss_kernel<<<NBLK, 256>>>(out);
}

// round 11
// speedup vs baseline: 1.0645x; 1.0645x over previous
#include <cuda_runtime.h>

#define N 384
#define D 256
#define EPSF 1e-12f
#define NTILES 21
#define NUNITS (NTILES * N)   // 8064
#define NBLK 296              // 148 SMs x 2 blocks, all co-resident
#define NGRAM 144             // gram tile-units: 72 per side (6 x 12)
#define BI 8                  // i-batch staged in smem

typedef unsigned long long u64;

// scratch (no allocation allowed)
__device__ float  g_Gs[N * N];
__device__ float  g_Gt[N * N];
__device__ float  g_ps[N * N];     // inv_ij (student)
__device__ float  g_cps[N * N];    // (G_ii - G_ij) * inv_ij
__device__ float  g_nrqs[N * N];   // -G_ij * inv_ij
__device__ float  g_pt[N * N];
__device__ float  g_cpt[N * N];
__device__ float  g_nrqt[N * N];
__device__ double g_sum;
__device__ int    g_cnt;
__device__ int    g_bar;

// upper-triangle 64x64 tile enumeration (a <= b), 21 tiles over a 6x6 grid
__constant__ int c_TA[NTILES] = {0,0,0,0,0,0,1,1,1,1,1,2,2,2,2,3,3,3,4,4,5};
__constant__ int c_TB[NTILES] = {0,1,2,3,4,5,1,2,3,4,5,2,3,4,5,3,4,5,4,5,5};

// ---------------------------------------------------------------------------
// packed f32x2 helpers (sm_103a)
__device__ __forceinline__ u64 pk(float lo, float hi) {
    union { float2 f; u64 u; } t; t.f.x = lo; t.f.y = hi; return t.u;
}
__device__ __forceinline__ float2 upk(u64 v) {
    union { float2 f; u64 u; } t; t.u = v; return t.f;
}
union F4U2 { float4 f; ulonglong2 u; };

__device__ __forceinline__ u64 mul2(u64 a, u64 b) {
    u64 r; asm("mul.rn.f32x2 %0,%1,%2;" : "=l"(r) : "l"(a), "l"(b)); return r;
}
__device__ __forceinline__ u64 fma2(u64 a, u64 b, u64 c) {
    u64 r; asm("fma.rn.f32x2 %0,%1,%2,%3;" : "=l"(r) : "l"(a), "l"(b), "l"(c)); return r;
}

// smem buffer shared by both phases
#define SM_AS 0                      // 2*32*34*4 = 8704
#define SM_BS 8704                   // 2*32*68*4 = 17408
#define SM_DA 26112                  // 32*4
#define SM_DB 26240                  // 64*4
#define SM_STAGE 0                   // 8*BI*64*4 = 16384
#define SM_RED 16384                 // 256*4
#define SM_BYTES 26624

// ---------------------------------------------------------------------------
__global__ void __launch_bounds__(256, 2) rkd_fused_kernel(const float* __restrict__ S,
                                                           const float* __restrict__ T,
                                                           float* __restrict__ out) {
    __shared__ __align__(16) char smbuf[SM_BYTES];

    int tid = threadIdx.x;
    int b = blockIdx.x;

    // =======================================================================
    // Phase 1: gram + prep (blocks 0..NGRAM-1, one 32x64 tile each)
    // =======================================================================
    if (b < NGRAM) {
        int z = b / 72;            // 0: student, 1: teacher
        int lin = b - z * 72;      // 0..71
        int bx = lin % 6;          // k-tile (64 wide), 0..5
        int by = lin / 6;          // j-tile (32 tall), 0..11

        const float* __restrict__ E = (z == 0) ? S : T;
        float* __restrict__ G  = (z == 0) ? g_Gs   : g_Gt;
        float* __restrict__ P  = (z == 0) ? g_ps   : g_pt;
        float* __restrict__ CP = (z == 0) ? g_cps  : g_cpt;
        float* __restrict__ NR = (z == 0) ? g_nrqs : g_nrqt;

        typedef float (*AsT)[32][34];
        typedef float (*BsT)[32][68];
        AsT As = (AsT)(smbuf + SM_AS);
        BsT Bs = (BsT)(smbuf + SM_BS);
        float* dA = (float*)(smbuf + SM_DA);
        float* dB = (float*)(smbuf + SM_DB);

        if (b == 0 && tid == 0) g_sum = 0.0;

        int ty = tid >> 4, tx = tid & 15;
        int row = tid >> 3;
        int c4 = (tid & 7) * 4;

        int tj = by * 32, tk = bx * 64;

        const float* pA  = &E[(tj + row) * D + c4];
        const float* pB0 = &E[(tk + row) * D + c4];
        const float* pB1 = &E[(tk + 32 + row) * D + c4];

        float acc[2][4];
#pragma unroll
        for (int r = 0; r < 2; r++)
#pragma unroll
            for (int c = 0; c < 4; c++) acc[r][c] = 0.f;

        float ssA = 0.f, ssB0 = 0.f, ssB1 = 0.f;

        float4 av  = *reinterpret_cast<const float4*>(pA);
        float4 bv0 = *reinterpret_cast<const float4*>(pB0);
        float4 bv1 = *reinterpret_cast<const float4*>(pB1);
        As[0][c4 + 0][row] = av.x;  As[0][c4 + 1][row] = av.y;
        As[0][c4 + 2][row] = av.z;  As[0][c4 + 3][row] = av.w;
        Bs[0][c4 + 0][row] = bv0.x; Bs[0][c4 + 1][row] = bv0.y;
        Bs[0][c4 + 2][row] = bv0.z; Bs[0][c4 + 3][row] = bv0.w;
        Bs[0][c4 + 0][row + 32] = bv1.x; Bs[0][c4 + 1][row + 32] = bv1.y;
        Bs[0][c4 + 2][row + 32] = bv1.z; Bs[0][c4 + 3][row + 32] = bv1.w;
        ssA  = fmaf(av.x,  av.x,  fmaf(av.y,  av.y,  fmaf(av.z,  av.z,  fmaf(av.w,  av.w,  ssA))));
        ssB0 = fmaf(bv0.x, bv0.x, fmaf(bv0.y, bv0.y, fmaf(bv0.z, bv0.z, fmaf(bv0.w, bv0.w, ssB0))));
        ssB1 = fmaf(bv1.x, bv1.x, fmaf(bv1.y, bv1.y, fmaf(bv1.z, bv1.z, fmaf(bv1.w, bv1.w, ssB1))));
        __syncthreads();

#pragma unroll
        for (int chunk = 0; chunk < D / 32; chunk++) {
            int cur = chunk & 1;
            bool more = (chunk < D / 32 - 1);
            if (more) {
                int off = (chunk + 1) * 32;
                av  = *reinterpret_cast<const float4*>(pA  + off);
                bv0 = *reinterpret_cast<const float4*>(pB0 + off);
                bv1 = *reinterpret_cast<const float4*>(pB1 + off);
            }
#pragma unroll
            for (int kk = 0; kk < 32; kk++) {
                float2 a2 = *reinterpret_cast<const float2*>(&As[cur][kk][ty * 2]);
                float4 b4 = *reinterpret_cast<const float4*>(&Bs[cur][kk][tx * 4]);
                acc[0][0] = fmaf(a2.x, b4.x, acc[0][0]);
                acc[0][1] = fmaf(a2.x, b4.y, acc[0][1]);
                acc[0][2] = fmaf(a2.x, b4.z, acc[0][2]);
                acc[0][3] = fmaf(a2.x, b4.w, acc[0][3]);
                acc[1][0] = fmaf(a2.y, b4.x, acc[1][0]);
                acc[1][1] = fmaf(a2.y, b4.y, acc[1][1]);
                acc[1][2] = fmaf(a2.y, b4.z, acc[1][2]);
                acc[1][3] = fmaf(a2.y, b4.w, acc[1][3]);
            }
            if (more) {
                int nb = cur ^ 1;
                As[nb][c4 + 0][row] = av.x;  As[nb][c4 + 1][row] = av.y;
                As[nb][c4 + 2][row] = av.z;  As[nb][c4 + 3][row] = av.w;
                Bs[nb][c4 + 0][row] = bv0.x; Bs[nb][c4 + 1][row] = bv0.y;
                Bs[nb][c4 + 2][row] = bv0.z; Bs[nb][c4 + 3][row] = bv0.w;
                Bs[nb][c4 + 0][row + 32] = bv1.x; Bs[nb][c4 + 1][row + 32] = bv1.y;
                Bs[nb][c4 + 2][row + 32] = bv1.z; Bs[nb][c4 + 3][row + 32] = bv1.w;
                ssA  = fmaf(av.x,  av.x,  fmaf(av.y,  av.y,  fmaf(av.z,  av.z,  fmaf(av.w,  av.w,  ssA))));
                ssB0 = fmaf(bv0.x, bv0.x, fmaf(bv0.y, bv0.y, fmaf(bv0.z, bv0.z, fmaf(bv0.w, bv0.w, ssB0))));
                ssB1 = fmaf(bv1.x, bv1.x, fmaf(bv1.y, bv1.y, fmaf(bv1.z, bv1.z, fmaf(bv1.w, bv1.w, ssB1))));
            }
            __syncthreads();
        }

#pragma unroll
        for (int m = 4; m > 0; m >>= 1) {
            ssA  += __shfl_xor_sync(0xffffffffu, ssA,  m, 8);
            ssB0 += __shfl_xor_sync(0xffffffffu, ssB0, m, 8);
            ssB1 += __shfl_xor_sync(0xffffffffu, ssB1, m, 8);
        }
        if ((tid & 7) == 0) {
            dA[row] = ssA;
            dB[row] = ssB0;
            dB[row + 32] = ssB1;
        }
        __syncthreads();

        int jg = tj + ty * 2;
        int kg = tk + tx * 4;
#pragma unroll
        for (int r = 0; r < 2; r++) {
            int ig = jg + r;
            float di = dA[ty * 2 + r];

            float4 pv, cv, nv;
            float* pp = &pv.x; float* cp = &cv.x; float* np = &nv.x;
#pragma unroll
            for (int c = 0; c < 4; c++) {
                float gij = acc[r][c];
                float dj = dB[tx * 4 + c];
                float cs = di - gij;
                float n2 = fmaxf((dj - gij) + cs, 0.f);
                float p = (ig == kg + c) ? 0.f : (1.f / fmaxf(sqrtf(n2), EPSF));
                pp[c] = p;
                cp[c] = cs * p;
                np[c] = -gij * p;
            }
            *reinterpret_cast<float4*>(&G[ig * N + kg]) =
                make_float4(acc[r][0], acc[r][1], acc[r][2], acc[r][3]);
            *reinterpret_cast<float4*>(&P[ig * N + kg])  = pv;
            *reinterpret_cast<float4*>(&CP[ig * N + kg]) = cv;
            *reinterpret_cast<float4*>(&NR[ig * N + kg]) = nv;
        }

        // arrive at grid barrier
        __syncthreads();
        if (tid == 0) {
            __threadfence();
            atomicAdd(&g_bar, 1);
        }
    }

    // =======================================================================
    // Grid barrier: wait until all NGRAM gram blocks have published.
    // All NBLK blocks are co-resident (occ 2), so spinning is safe.
    // =======================================================================
    if (tid == 0) {
        while (*((volatile int*)&g_bar) < NGRAM) __nanosleep(64);
        __threadfence();
    }
    __syncthreads();

    // =======================================================================
    // Phase 2: angle loss (all NBLK blocks) — R8 body.
    // =======================================================================
    typedef float (*StT)[BI][64];
    StT stage = (StT)(smbuf + SM_STAGE);
    float* red = (float*)(smbuf + SM_RED);

    int ty = tid >> 4, tx = tid & 15;

    int jl_col4 = (tid & 15) * 4;
    int l_ii    = (tid >> 4) & 7;
    int l_hi    = tid >> 7;

    int u0 = (b * NUNITS) / NBLK;
    int u1 = ((b + 1) * NUNITS) / NBLK;
    int tile = u0 / N;
    int i = u0 - tile * N;
    int remaining = u1 - u0;

    const u64 NEG1 = 0xBF800000BF800000ULL;  // {-1.f, -1.f}

    float wacc = 0.f;

    while (remaining > 0) {
        int cnt = min(N - i, remaining);
        remaining -= cnt;

        int tj = c_TA[tile] * 64;
        int tk = c_TB[tile] * 64;
        int jq = tj + ty * 4;
        int kq = tk + tx * 4;

        const float* src0 = (l_hi ? g_cps  + tj : g_ps + tj) + jl_col4;
        const float* src1 = (l_hi ? g_nrqs + tk : g_ps + tk) + jl_col4;
        const float* src2 = (l_hi ? g_cpt  + tj : g_pt + tj) + jl_col4;
        const float* src3 = (l_hi ? g_nrqt + tk : g_pt + tk) + jl_col4;

        // G microtile packed along k (free reinterpret of LDG.128)
        u64 G2s[4][2], G2t[4][2];
#pragma unroll
        for (int jj = 0; jj < 4; jj++) {
            ulonglong2 vs = *reinterpret_cast<const ulonglong2*>(&g_Gs[(jq + jj) * N + kq]);
            ulonglong2 vt = *reinterpret_cast<const ulonglong2*>(&g_Gt[(jq + jj) * N + kq]);
            G2s[jj][0] = vs.x; G2s[jj][1] = vs.y;
            G2t[jj][0] = vt.x; G2t[jj][1] = vt.y;
        }

        float acc0 = 0.f, acc1 = 0.f;

        for (int s = 0; s < cnt; s += BI) {
            {
                int ir = min(i + s + l_ii, N - 1) * N;
                float4 v0 = *reinterpret_cast<const float4*>(src0 + ir);
                float4 v1 = *reinterpret_cast<const float4*>(src1 + ir);
                float4 v2 = *reinterpret_cast<const float4*>(src2 + ir);
                float4 v3 = *reinterpret_cast<const float4*>(src3 + ir);
                *reinterpret_cast<float4*>(&stage[0 + l_hi][l_ii][jl_col4]) = v0;
                *reinterpret_cast<float4*>(&stage[2 + l_hi][l_ii][jl_col4]) = v1;
                *reinterpret_cast<float4*>(&stage[4 + l_hi][l_ii][jl_col4]) = v2;
                *reinterpret_cast<float4*>(&stage[6 + l_hi][l_ii][jl_col4]) = v3;
            }
            __syncthreads();

            int bi = min(BI, cnt - s);
            for (int ii = 0; ii < bi; ii++) {
                float4 pj_s = *reinterpret_cast<const float4*>(&stage[0][ii][ty * 4]);
                float4 cj_s = *reinterpret_cast<const float4*>(&stage[1][ii][ty * 4]);
                F4U2 qk_s; qk_s.f = *reinterpret_cast<const float4*>(&stage[2][ii][tx * 4]);
                F4U2 nr_s; nr_s.f = *reinterpret_cast<const float4*>(&stage[3][ii][tx * 4]);
                float4 pj_t = *reinterpret_cast<const float4*>(&stage[4][ii][ty * 4]);
                float4 cj_t = *reinterpret_cast<const float4*>(&stage[5][ii][ty * 4]);
                F4U2 qk_t; qk_t.f = *reinterpret_cast<const float4*>(&stage[6][ii][tx * 4]);
                F4U2 nr_t; nr_t.f = *reinterpret_cast<const float4*>(&stage[7][ii][tx * 4]);

                u64 q2s[2] = { qk_s.u.x, qk_s.u.y };
                u64 n2s[2] = { nr_s.u.x, nr_s.u.y };
                u64 q2t[2] = { qk_t.u.x, qk_t.u.y };
                u64 n2t[2] = { nr_t.u.x, nr_t.u.y };

                float pjs_a[4] = {pj_s.x, pj_s.y, pj_s.z, pj_s.w};
                float cjs_a[4] = {cj_s.x, cj_s.y, cj_s.z, cj_s.w};
                float pjt_a[4] = {pj_t.x, pj_t.y, pj_t.z, pj_t.w};
                float cjt_a[4] = {cj_t.x, cj_t.y, cj_t.z, cj_t.w};

#pragma unroll
                for (int jj = 0; jj < 4; jj++) {
                    u64 p2s = pk(pjs_a[jj], pjs_a[jj]);
                    u64 c2s = pk(cjs_a[jj], cjs_a[jj]);
                    u64 p2t = pk(pjt_a[jj], pjt_a[jj]);
                    u64 c2t = pk(cjt_a[jj], cjt_a[jj]);
#pragma unroll
                    for (int p = 0; p < 2; p++) {
                        u64 t2s = fma2(p2s, G2s[jj][p], c2s);
                        u64 m2s = mul2(n2s[p], p2s);
                        u64 a2s = fma2(q2s[p], t2s, m2s);
                        u64 t2t = fma2(p2t, G2t[jj][p], c2t);
                        u64 m2t = mul2(n2t[p], p2t);
                        u64 a2t = fma2(q2t[p], t2t, m2t);
                        u64 d2  = fma2(a2t, NEG1, a2s);      // as - at
                        float2 d = upk(d2);
                        float x0 = fabsf(d.x), x1 = fabsf(d.y);
                        float y0 = fminf(x0, 1.f), y1 = fminf(x1, 1.f);
                        float t0 = fmaf(y0, -0.5f, x0);
                        float t1 = fmaf(y1, -0.5f, x1);
                        acc0 = fmaf(y0, t0, acc0);
                        acc1 = fmaf(y1, t1, acc1);
                    }
                }
            }
            __syncthreads();
        }

        float w = (c_TA[tile] == c_TB[tile]) ? 1.f : 2.f;
        wacc = fmaf(w, acc0 + acc1, wacc);
        tile++;
        i = 0;
    }

    // block reduction
    red[tid] = wacc;
    __syncthreads();
#pragma unroll
    for (int s = 128; s > 0; s >>= 1) {
        if (tid < s) red[tid] += red[tid + s];
        __syncthreads();
    }
    if (tid == 0) {
        atomicAdd(&g_sum, (double)red[0]);
        __threadfence();
        int t = atomicAdd(&g_cnt, 1);
        if (t == NBLK - 1) {
            double v = atomicAdd(&g_sum, 0.0);
            double n3 = (double)N * (double)N * (double)N;
            out[0] = (float)(v / n3);
            // reset counters for the next graph replay
            __threadfence();
            g_cnt = 0;
            *((volatile int*)&g_bar) = 0;
        }
    }
}

// ---------------------------------------------------------------------------
extern "C" void kernel_launch(void* const* d_in, const int* in_sizes, int n_in,
                              void* d_out, int out_size) {
    const float* student = (const float*)d_in[0];
    const float* teacher = (const float*)d_in[1];
    float* out = (float*)d_out;

    rkd_fused_kernel<<<NBLK, 256>>>(student, teacher, out);
}

// round 12
// speedup vs baseline: 1.0656x; 1.0010x over previous
#include <cuda_runtime.h>

#define N 384
#define D 256
#define EPSF 1e-12f
#define NTILES 21
#define NUNITS (NTILES * N)   // 8064
#define NBLK 296              // 148 SMs x 2 blocks, all co-resident
#define NGRAM 144             // gram tile-units: 72 per side (6 x 12)
#define BI 8                  // i-batch staged in smem

typedef unsigned long long u64;

// scratch (no allocation allowed)
__device__ float  g_Gs[N * N];
__device__ float  g_Gt[N * N];
__device__ float  g_ps[N * N];     // inv_ij (student)
__device__ float  g_cps[N * N];    // (G_ii - G_ij) * inv_ij
__device__ float  g_nrqs[N * N];   // -G_ij * inv_ij
__device__ float  g_pt[N * N];
__device__ float  g_cpt[N * N];
__device__ float  g_nrqt[N * N];
__device__ double g_sum;
__device__ int    g_cnt;
__device__ int    g_bar;

// upper-triangle 64x64 tile enumeration (a <= b), 21 tiles over a 6x6 grid
__constant__ int c_TA[NTILES] = {0,0,0,0,0,0,1,1,1,1,1,2,2,2,2,3,3,3,4,4,5};
__constant__ int c_TB[NTILES] = {0,1,2,3,4,5,1,2,3,4,5,2,3,4,5,3,4,5,4,5,5};

// ---------------------------------------------------------------------------
// packed f32x2 helpers (sm_103a)
__device__ __forceinline__ u64 pk(float lo, float hi) {
    union { float2 f; u64 u; } t; t.f.x = lo; t.f.y = hi; return t.u;
}
__device__ __forceinline__ float2 upk(u64 v) {
    union { float2 f; u64 u; } t; t.u = v; return t.f;
}
union F4U2 { float4 f; ulonglong2 u; };

__device__ __forceinline__ u64 mul2(u64 a, u64 b) {
    u64 r; asm("mul.rn.f32x2 %0,%1,%2;" : "=l"(r) : "l"(a), "l"(b)); return r;
}
__device__ __forceinline__ u64 fma2(u64 a, u64 b, u64 c) {
    u64 r; asm("fma.rn.f32x2 %0,%1,%2,%3;" : "=l"(r) : "l"(a), "l"(b), "l"(c)); return r;
}

// smem buffer shared by both phases
// phase 1: As 8704 | Bs 17408 | dA 128 | dB 256        = 26496
// phase 2: stage[2][8][BI][64] = 32768 | red 1024      = 33792
#define SM_AS 0
#define SM_BS 8704
#define SM_DA 26112
#define SM_DB 26240
#define SM_STAGE 0
#define SM_RED 32768
#define SM_BYTES 33792

// ---------------------------------------------------------------------------
__global__ void __launch_bounds__(256, 2) rkd_fused_kernel(const float* __restrict__ S,
                                                           const float* __restrict__ T,
                                                           float* __restrict__ out) {
    __shared__ __align__(16) char smbuf[SM_BYTES];

    int tid = threadIdx.x;
    int b = blockIdx.x;

    // =======================================================================
    // Phase 1: gram + prep (blocks 0..NGRAM-1, one 32x64 tile each)
    // =======================================================================
    if (b < NGRAM) {
        int z = b / 72;            // 0: student, 1: teacher
        int lin = b - z * 72;      // 0..71
        int bx = lin % 6;          // k-tile (64 wide), 0..5
        int by = lin / 6;          // j-tile (32 tall), 0..11

        const float* __restrict__ E = (z == 0) ? S : T;
        float* __restrict__ G  = (z == 0) ? g_Gs   : g_Gt;
        float* __restrict__ P  = (z == 0) ? g_ps   : g_pt;
        float* __restrict__ CP = (z == 0) ? g_cps  : g_cpt;
        float* __restrict__ NR = (z == 0) ? g_nrqs : g_nrqt;

        typedef float (*AsT)[32][34];
        typedef float (*BsT)[32][68];
        AsT As = (AsT)(smbuf + SM_AS);
        BsT Bs = (BsT)(smbuf + SM_BS);
        float* dA = (float*)(smbuf + SM_DA);
        float* dB = (float*)(smbuf + SM_DB);

        if (b == 0 && tid == 0) g_sum = 0.0;

        int ty = tid >> 4, tx = tid & 15;
        int row = tid >> 3;
        int c4 = (tid & 7) * 4;

        int tj = by * 32, tk = bx * 64;

        const float* pA  = &E[(tj + row) * D + c4];
        const float* pB0 = &E[(tk + row) * D + c4];
        const float* pB1 = &E[(tk + 32 + row) * D + c4];

        float acc[2][4];
#pragma unroll
        for (int r = 0; r < 2; r++)
#pragma unroll
            for (int c = 0; c < 4; c++) acc[r][c] = 0.f;

        float ssA = 0.f, ssB0 = 0.f, ssB1 = 0.f;

        float4 av  = *reinterpret_cast<const float4*>(pA);
        float4 bv0 = *reinterpret_cast<const float4*>(pB0);
        float4 bv1 = *reinterpret_cast<const float4*>(pB1);
        As[0][c4 + 0][row] = av.x;  As[0][c4 + 1][row] = av.y;
        As[0][c4 + 2][row] = av.z;  As[0][c4 + 3][row] = av.w;
        Bs[0][c4 + 0][row] = bv0.x; Bs[0][c4 + 1][row] = bv0.y;
        Bs[0][c4 + 2][row] = bv0.z; Bs[0][c4 + 3][row] = bv0.w;
        Bs[0][c4 + 0][row + 32] = bv1.x; Bs[0][c4 + 1][row + 32] = bv1.y;
        Bs[0][c4 + 2][row + 32] = bv1.z; Bs[0][c4 + 3][row + 32] = bv1.w;
        ssA  = fmaf(av.x,  av.x,  fmaf(av.y,  av.y,  fmaf(av.z,  av.z,  fmaf(av.w,  av.w,  ssA))));
        ssB0 = fmaf(bv0.x, bv0.x, fmaf(bv0.y, bv0.y, fmaf(bv0.z, bv0.z, fmaf(bv0.w, bv0.w, ssB0))));
        ssB1 = fmaf(bv1.x, bv1.x, fmaf(bv1.y, bv1.y, fmaf(bv1.z, bv1.z, fmaf(bv1.w, bv1.w, ssB1))));
        __syncthreads();

#pragma unroll
        for (int chunk = 0; chunk < D / 32; chunk++) {
            int cur = chunk & 1;
            bool more = (chunk < D / 32 - 1);
            if (more) {
                int off = (chunk + 1) * 32;
                av  = *reinterpret_cast<const float4*>(pA  + off);
                bv0 = *reinterpret_cast<const float4*>(pB0 + off);
                bv1 = *reinterpret_cast<const float4*>(pB1 + off);
            }
#pragma unroll
            for (int kk = 0; kk < 32; kk++) {
                float2 a2 = *reinterpret_cast<const float2*>(&As[cur][kk][ty * 2]);
                float4 b4 = *reinterpret_cast<const float4*>(&Bs[cur][kk][tx * 4]);
                acc[0][0] = fmaf(a2.x, b4.x, acc[0][0]);
                acc[0][1] = fmaf(a2.x, b4.y, acc[0][1]);
                acc[0][2] = fmaf(a2.x, b4.z, acc[0][2]);
                acc[0][3] = fmaf(a2.x, b4.w, acc[0][3]);
                acc[1][0] = fmaf(a2.y, b4.x, acc[1][0]);
                acc[1][1] = fmaf(a2.y, b4.y, acc[1][1]);
                acc[1][2] = fmaf(a2.y, b4.z, acc[1][2]);
                acc[1][3] = fmaf(a2.y, b4.w, acc[1][3]);
            }
            if (more) {
                int nb = cur ^ 1;
                As[nb][c4 + 0][row] = av.x;  As[nb][c4 + 1][row] = av.y;
                As[nb][c4 + 2][row] = av.z;  As[nb][c4 + 3][row] = av.w;
                Bs[nb][c4 + 0][row] = bv0.x; Bs[nb][c4 + 1][row] = bv0.y;
                Bs[nb][c4 + 2][row] = bv0.z; Bs[nb][c4 + 3][row] = bv0.w;
                Bs[nb][c4 + 0][row + 32] = bv1.x; Bs[nb][c4 + 1][row + 32] = bv1.y;
                Bs[nb][c4 + 2][row + 32] = bv1.z; Bs[nb][c4 + 3][row + 32] = bv1.w;
                ssA  = fmaf(av.x,  av.x,  fmaf(av.y,  av.y,  fmaf(av.z,  av.z,  fmaf(av.w,  av.w,  ssA))));
                ssB0 = fmaf(bv0.x, bv0.x, fmaf(bv0.y, bv0.y, fmaf(bv0.z, bv0.z, fmaf(bv0.w, bv0.w, ssB0))));
                ssB1 = fmaf(bv1.x, bv1.x, fmaf(bv1.y, bv1.y, fmaf(bv1.z, bv1.z, fmaf(bv1.w, bv1.w, ssB1))));
            }
            __syncthreads();
        }

#pragma unroll
        for (int m = 4; m > 0; m >>= 1) {
            ssA  += __shfl_xor_sync(0xffffffffu, ssA,  m, 8);
            ssB0 += __shfl_xor_sync(0xffffffffu, ssB0, m, 8);
            ssB1 += __shfl_xor_sync(0xffffffffu, ssB1, m, 8);
        }
        if ((tid & 7) == 0) {
            dA[row] = ssA;
            dB[row] = ssB0;
            dB[row + 32] = ssB1;
        }
        __syncthreads();

        int jg = tj + ty * 2;
        int kg = tk + tx * 4;
#pragma unroll
        for (int r = 0; r < 2; r++) {
            int ig = jg + r;
            float di = dA[ty * 2 + r];

            float4 pv, cv, nv;
            float* pp = &pv.x; float* cp = &cv.x; float* np = &nv.x;
#pragma unroll
            for (int c = 0; c < 4; c++) {
                float gij = acc[r][c];
                float dj = dB[tx * 4 + c];
                float cs = di - gij;
                float n2 = fmaxf((dj - gij) + cs, 0.f);
                float p = (ig == kg + c) ? 0.f : (1.f / fmaxf(sqrtf(n2), EPSF));
                pp[c] = p;
                cp[c] = cs * p;
                np[c] = -gij * p;
            }
            *reinterpret_cast<float4*>(&G[ig * N + kg]) =
                make_float4(acc[r][0], acc[r][1], acc[r][2], acc[r][3]);
            *reinterpret_cast<float4*>(&P[ig * N + kg])  = pv;
            *reinterpret_cast<float4*>(&CP[ig * N + kg]) = cv;
            *reinterpret_cast<float4*>(&NR[ig * N + kg]) = nv;
        }

        // arrive at grid barrier
        __syncthreads();
        if (tid == 0) {
            __threadfence();
            atomicAdd(&g_bar, 1);
        }
    }

    // =======================================================================
    // Grid barrier: wait until all NGRAM gram blocks have published.
    // All NBLK blocks are co-resident (occ 2), so spinning is safe.
    // =======================================================================
    if (tid == 0) {
        while (*((volatile int*)&g_bar) < NGRAM) __nanosleep(64);
        __threadfence();
    }
    __syncthreads();

    // =======================================================================
    // Phase 2: angle loss. Double-buffered staging (1 sync/batch), 4 accs.
    // =======================================================================
    // stage[buf][slice][ii][64]: slices 0:ps_j 1:cps_j 2:ps_k 3:nrqs_k
    //                                   4:pt_j 5:cpt_j 6:pt_k 7:nrqt_k
    typedef float (*StT)[8][BI][64];
    StT stage = (StT)(smbuf + SM_STAGE);
    float* red = (float*)(smbuf + SM_RED);

    int ty = tid >> 4, tx = tid & 15;

    int jl_col4 = (tid & 15) * 4;
    int l_ii    = (tid >> 4) & 7;
    int l_hi    = tid >> 7;

    int u0 = (b * NUNITS) / NBLK;
    int u1 = ((b + 1) * NUNITS) / NBLK;
    int tile = u0 / N;
    int i = u0 - tile * N;
    int remaining = u1 - u0;

    const u64 NEG1 = 0xBF800000BF800000ULL;  // {-1.f, -1.f}

    float wacc = 0.f;

    while (remaining > 0) {
        int cnt = min(N - i, remaining);
        remaining -= cnt;

        int tj = c_TA[tile] * 64;
        int tk = c_TB[tile] * 64;
        int jq = tj + ty * 4;
        int kq = tk + tx * 4;

        const float* src0 = (l_hi ? g_cps  + tj : g_ps + tj) + jl_col4;
        const float* src1 = (l_hi ? g_nrqs + tk : g_ps + tk) + jl_col4;
        const float* src2 = (l_hi ? g_cpt  + tj : g_pt + tj) + jl_col4;
        const float* src3 = (l_hi ? g_nrqt + tk : g_pt + tk) + jl_col4;

        // G microtile packed along k (free reinterpret of LDG.128)
        u64 G2s[4][2], G2t[4][2];
#pragma unroll
        for (int jj = 0; jj < 4; jj++) {
            ulonglong2 vs = *reinterpret_cast<const ulonglong2*>(&g_Gs[(jq + jj) * N + kq]);
            ulonglong2 vt = *reinterpret_cast<const ulonglong2*>(&g_Gt[(jq + jj) * N + kq]);
            G2s[jj][0] = vs.x; G2s[jj][1] = vs.y;
            G2t[jj][0] = vt.x; G2t[jj][1] = vt.y;
        }

        float acc0 = 0.f, acc1 = 0.f, acc2 = 0.f, acc3 = 0.f;

        int nbatch = (cnt + BI - 1) / BI;

        // prologue: stage batch 0 into buf 0
        {
            int ir = min(i + l_ii, N - 1) * N;
            float4 v0 = *reinterpret_cast<const float4*>(src0 + ir);
            float4 v1 = *reinterpret_cast<const float4*>(src1 + ir);
            float4 v2 = *reinterpret_cast<const float4*>(src2 + ir);
            float4 v3 = *reinterpret_cast<const float4*>(src3 + ir);
            *reinterpret_cast<float4*>(&stage[0][0 + l_hi][l_ii][jl_col4]) = v0;
            *reinterpret_cast<float4*>(&stage[0][2 + l_hi][l_ii][jl_col4]) = v1;
            *reinterpret_cast<float4*>(&stage[0][4 + l_hi][l_ii][jl_col4]) = v2;
            *reinterpret_cast<float4*>(&stage[0][6 + l_hi][l_ii][jl_col4]) = v3;
        }
        __syncthreads();

        for (int bn = 0; bn < nbatch; bn++) {
            int cur = bn & 1;
            bool more = (bn + 1 < nbatch);

            // prefetch batch bn+1 into registers (LDG overlapped with compute)
            float4 w0, w1, w2, w3;
            if (more) {
                int ir = min(i + (bn + 1) * BI + l_ii, N - 1) * N;
                w0 = *reinterpret_cast<const float4*>(src0 + ir);
                w1 = *reinterpret_cast<const float4*>(src1 + ir);
                w2 = *reinterpret_cast<const float4*>(src2 + ir);
                w3 = *reinterpret_cast<const float4*>(src3 + ir);
            }

            int bi = min(BI, cnt - bn * BI);
            for (int ii = 0; ii < bi; ii++) {
                float4 pj_s = *reinterpret_cast<const float4*>(&stage[cur][0][ii][ty * 4]);
                float4 cj_s = *reinterpret_cast<const float4*>(&stage[cur][1][ii][ty * 4]);
                F4U2 qk_s; qk_s.f = *reinterpret_cast<const float4*>(&stage[cur][2][ii][tx * 4]);
                F4U2 nr_s; nr_s.f = *reinterpret_cast<const float4*>(&stage[cur][3][ii][tx * 4]);
                float4 pj_t = *reinterpret_cast<const float4*>(&stage[cur][4][ii][ty * 4]);
                float4 cj_t = *reinterpret_cast<const float4*>(&stage[cur][5][ii][ty * 4]);
                F4U2 qk_t; qk_t.f = *reinterpret_cast<const float4*>(&stage[cur][6][ii][tx * 4]);
                F4U2 nr_t; nr_t.f = *reinterpret_cast<const float4*>(&stage[cur][7][ii][tx * 4]);

                u64 q2s[2] = { qk_s.u.x, qk_s.u.y };
                u64 n2s[2] = { nr_s.u.x, nr_s.u.y };
                u64 q2t[2] = { qk_t.u.x, qk_t.u.y };
                u64 n2t[2] = { nr_t.u.x, nr_t.u.y };

                float pjs_a[4] = {pj_s.x, pj_s.y, pj_s.z, pj_s.w};
                float cjs_a[4] = {cj_s.x, cj_s.y, cj_s.z, cj_s.w};
                float pjt_a[4] = {pj_t.x, pj_t.y, pj_t.z, pj_t.w};
                float cjt_a[4] = {cj_t.x, cj_t.y, cj_t.z, cj_t.w};

#pragma unroll
                for (int jj = 0; jj < 4; jj++) {
                    u64 p2s = pk(pjs_a[jj], pjs_a[jj]);
                    u64 c2s = pk(cjs_a[jj], cjs_a[jj]);
                    u64 p2t = pk(pjt_a[jj], pjt_a[jj]);
                    u64 c2t = pk(cjt_a[jj], cjt_a[jj]);
#pragma unroll
                    for (int p = 0; p < 2; p++) {
                        u64 t2s = fma2(p2s, G2s[jj][p], c2s);
                        u64 m2s = mul2(n2s[p], p2s);
                        u64 a2s = fma2(q2s[p], t2s, m2s);
                        u64 t2t = fma2(p2t, G2t[jj][p], c2t);
                        u64 m2t = mul2(n2t[p], p2t);
                        u64 a2t = fma2(q2t[p], t2t, m2t);
                        u64 d2  = fma2(a2t, NEG1, a2s);      // as - at
                        float2 d = upk(d2);
                        float x0 = fabsf(d.x), x1 = fabsf(d.y);
                        float y0 = fminf(x0, 1.f), y1 = fminf(x1, 1.f);
                        float t0 = fmaf(y0, -0.5f, x0);
                        float t1 = fmaf(y1, -0.5f, x1);
                        // 4 accumulators: split by jj parity x p
                        if (((jj & 1) << 1 | p) == 0)      { acc0 = fmaf(y0, t0, acc0); acc0 = fmaf(y1, t1, acc0); }
                        else if (((jj & 1) << 1 | p) == 1) { acc1 = fmaf(y0, t0, acc1); acc1 = fmaf(y1, t1, acc1); }
                        else if (((jj & 1) << 1 | p) == 2) { acc2 = fmaf(y0, t0, acc2); acc2 = fmaf(y1, t1, acc2); }
                        else                               { acc3 = fmaf(y0, t0, acc3); acc3 = fmaf(y1, t1, acc3); }
                    }
                }
            }

            if (more) {
                int nb = cur ^ 1;
                *reinterpret_cast<float4*>(&stage[nb][0 + l_hi][l_ii][jl_col4]) = w0;
                *reinterpret_cast<float4*>(&stage[nb][2 + l_hi][l_ii][jl_col4]) = w1;
                *reinterpret_cast<float4*>(&stage[nb][4 + l_hi][l_ii][jl_col4]) = w2;
                *reinterpret_cast<float4*>(&stage[nb][6 + l_hi][l_ii][jl_col4]) = w3;
            }
            __syncthreads();
        }

        float w = (c_TA[tile] == c_TB[tile]) ? 1.f : 2.f;
        wacc = fmaf(w, (acc0 + acc1) + (acc2 + acc3), wacc);
        tile++;
        i = 0;
    }

    // block reduction
    red[tid] = wacc;
    __syncthreads();
#pragma unroll
    for (int s = 128; s > 0; s >>= 1) {
        if (tid < s) red[tid] += red[tid + s];
        __syncthreads();
    }
    if (tid == 0) {
        atomicAdd(&g_sum, (double)red[0]);
        __threadfence();
        int t = atomicAdd(&g_cnt, 1);
        if (t == NBLK - 1) {
            double v = atomicAdd(&g_sum, 0.0);
            double n3 = (double)N * (double)N * (double)N;
            out[0] = (float)(v / n3);
            // reset counters for the next graph replay
            __threadfence();
            g_cnt = 0;
            *((volatile int*)&g_bar) = 0;
        }
    }
}

// ---------------------------------------------------------------------------
extern "C" void kernel_launch(void* const* d_in, const int* in_sizes, int n_in,
                              void* d_out, int out_size) {
    const float* student = (const float*)d_in[0];
    const float* teacher = (const float*)d_in[1];
    float* out = (float*)d_out;

    rkd_fused_kernel<<<NBLK, 256>>>(student, teacher, out);
}